// round 5
// baseline (speedup 1.0000x reference)
#include <cuda_runtime.h>
#include <math.h>

#define D_DIM 300

__global__ __launch_bounds__(256, 8)
void multisense_kernel(const float4* __restrict__ V4,    // [VOCAB * D] float4 (senses innermost)
                       const float4* __restrict__ W4,    // [COVOCAB * D]
                       const float4* __restrict__ vb4,   // [VOCAB]
                       const float4* __restrict__ wb4,   // [COVOCAB]
                       const int* __restrict__ IJ,       // [B*2] int32
                       float* __restrict__ out,
                       int B)
{
    const int warp_id = blockIdx.x * (blockDim.x >> 5) + (threadIdx.x >> 5);
    if (warp_id >= B) return;
    const int lane = threadIdx.x & 31;

    const int i = __ldg(IJ + 2 * warp_id);
    const int j = __ldg(IJ + 2 * warp_id + 1);

    const float4* __restrict__ Vr = V4 + (long long)i * D_DIM;
    const float4* __restrict__ Wr = W4 + (long long)j * D_DIM;

    // acc[s*4+t] = sum_d W[j,d,s] * V[i,d,t]
    float acc[16];
#pragma unroll
    for (int k = 0; k < 16; k++) acc[k] = 0.0f;

#pragma unroll 1
    for (int d = lane; d < D_DIM; d += 32) {
        const float4 v = __ldg(Vr + d);
        const float4 w = __ldg(Wr + d);
        acc[0]  = fmaf(w.x, v.x, acc[0]);
        acc[1]  = fmaf(w.x, v.y, acc[1]);
        acc[2]  = fmaf(w.x, v.z, acc[2]);
        acc[3]  = fmaf(w.x, v.w, acc[3]);
        acc[4]  = fmaf(w.y, v.x, acc[4]);
        acc[5]  = fmaf(w.y, v.y, acc[5]);
        acc[6]  = fmaf(w.y, v.z, acc[6]);
        acc[7]  = fmaf(w.y, v.w, acc[7]);
        acc[8]  = fmaf(w.z, v.x, acc[8]);
        acc[9]  = fmaf(w.z, v.y, acc[9]);
        acc[10] = fmaf(w.z, v.z, acc[10]);
        acc[11] = fmaf(w.z, v.w, acc[11]);
        acc[12] = fmaf(w.w, v.x, acc[12]);
        acc[13] = fmaf(w.w, v.y, acc[13]);
        acc[14] = fmaf(w.w, v.z, acc[14]);
        acc[15] = fmaf(w.w, v.w, acc[15]);
    }

    // Warp butterfly reduction: every lane ends with the full 16 sums.
#pragma unroll
    for (int off = 16; off > 0; off >>= 1) {
#pragma unroll
        for (int k = 0; k < 16; k++)
            acc[k] += __shfl_xor_sync(0xffffffffu, acc[k], off);
    }

    if (lane == 0) {
        const float4 wb = __ldg(wb4 + j);  // bias over s
        const float4 vb = __ldg(vb4 + i);  // bias over t
        const float bs[4] = {wb.x, wb.y, wb.z, wb.w};
        const float bt[4] = {vb.x, vb.y, vb.z, vb.w};

        float vals[16];
        float m = -INFINITY;
#pragma unroll
        for (int s = 0; s < 4; s++) {
#pragma unroll
            for (int t = 0; t < 4; t++) {
                const float x = acc[s * 4 + t] + bs[s] + bt[t];
                vals[s * 4 + t] = x;
                m = fmaxf(m, x);
            }
        }
        float sum = 0.0f;
#pragma unroll
        for (int k = 0; k < 16; k++)
            sum += __expf(vals[k] - m);
        out[warp_id] = __logf(sum) + m;
    }
}

extern "C" void kernel_launch(void* const* d_in, const int* in_sizes, int n_in,
                              void* d_out, int out_size)
{
    const float4* V4      = (const float4*)d_in[0];
    const float4* W4      = (const float4*)d_in[1];
    const float4* vb4     = (const float4*)d_in[2];
    const float4* wb4     = (const float4*)d_in[3];
    const int* IJ         = (const int*)d_in[4];
    float* out            = (float*)d_out;

    const int B = in_sizes[4] / 2;  // IJ has B*2 elements

    const int warps_per_block = 8;           // 256 threads
    const int blocks = (B + warps_per_block - 1) / warps_per_block;
    multisense_kernel<<<blocks, warps_per_block * 32>>>(V4, W4, vb4, wb4, IJ, out, B);
}